// round 15
// baseline (speedup 1.0000x reference)
#include <cuda_runtime.h>
#include <cfloat>
#include <stdint.h>

// x [64,256,32,32] f32, codebook [1024,256] f32
#define D_DIM   256
#define HW_DIM  1024
#define NPIX    65536
#define KCODE   1024
#define TOT_ELEMS 16777216
#define NCTA    2048           // BM=32 -> 6.92 CTAs/slot -> 98.9% packing

typedef unsigned long long u64;

// Scratch (device globals; allocation-free)
__device__ float  g_cn[KCODE];
__device__ float  g_xn[NPIX];
__device__ double g_partial[NCTA];

// ===================== packed f32x2 helpers (sm_100+) =====================
__device__ __forceinline__ u64 fma2(u64 a, u64 b, u64 c) {
    u64 d;
    asm("fma.rn.f32x2 %0, %1, %2, %3;" : "=l"(d) : "l"(a), "l"(b), "l"(c));
    return d;
}
__device__ __forceinline__ u64 dup2(float v) {
    u64 d;
    asm("mov.b64 %0, {%1, %1};" : "=l"(d) : "f"(v));
    return d;
}
__device__ __forceinline__ float lo2(u64 v) {
    float l, h;
    asm("mov.b64 {%0, %1}, %2;" : "=f"(l), "=f"(h) : "l"(v));
    return l;
}
__device__ __forceinline__ float hi2(u64 v) {
    float l, h;
    asm("mov.b64 {%0, %1}, %2;" : "=f"(l), "=f"(h) : "l"(v));
    return h;
}

// B smem column swizzle (round-9 validated): code c at word c + 4*(c>>5).
// Chunk = 256 codes -> max word bcol(255) = 283; pitch 284. Reader base
// rcol = tx*16 + 4*(tx>>1): per 8-lane LDS.128 phase the bank bases
// {0,16,4,20,8,24,12,28} partition all 32 banks -> conflict-free.
#define BPITCH 284
__device__ __forceinline__ int bcol(int c) { return c + 4 * (c >> 5); }

// Dynamic smem layout (bytes)
#define OFF_AS   0                       // As[2][16][32]  f32 = 4096
#define OFF_BS   4096                    // Bs[2][16][284] f32 = 36352
#define OFF_CNS  40448                   // 1024 f32 = 4096
#define OFF_XNS  44544                   // 32 f32
#define OFF_BV   44672                   // 32 f32
#define OFF_BI   44800                   // 32 i32
#define OFF_RED  44928                   // 256 f64 = 2048
#define SMEMB    81920                   // forces occupancy 2 (3x > 228KB)

// ---------------------------------------------------------------------------
// norms (scalar-sequential order — bit-exact-validated in round 2)
// ---------------------------------------------------------------------------
__global__ void cnorm_kernel(const float* __restrict__ cb) {
    int k = blockIdx.x * 256 + threadIdx.x;
    const float* row = cb + (size_t)k * D_DIM;
    float s = 0.f;
    for (int d = 0; d < D_DIM; d++) s = __fadd_rn(s, __fmul_rn(row[d], row[d]));
    g_cn[k] = s;
}
__global__ void xnorm_kernel(const float* __restrict__ x) {
    int b = blockIdx.x, t = threadIdx.x;
    const float* xb = x + (size_t)b * D_DIM * HW_DIM + t * 4;
    float sa[4] = {0.f, 0.f, 0.f, 0.f};
    for (int d = 0; d < D_DIM; d++) {
        float4 v = *(const float4*)(xb + (size_t)d * HW_DIM);
        sa[0] = __fadd_rn(sa[0], __fmul_rn(v.x, v.x));
        sa[1] = __fadd_rn(sa[1], __fmul_rn(v.y, v.y));
        sa[2] = __fadd_rn(sa[2], __fmul_rn(v.z, v.z));
        sa[3] = __fadd_rn(sa[3], __fmul_rn(v.w, v.w));
    }
    int p = b * HW_DIM + t * 4;
#pragma unroll
    for (int j = 0; j < 4; j++) g_xn[p + j] = sa[j];
}

// ---------------------------------------------------------------------------
// Main VQ: round-13 FFMA2 core retiled to 32 px/CTA with 256-code chunks
// (tile accounting now consistent: 256 thr x (2px x 16 codes) = 32 x 256).
// Double-buffered, 1 barrier/k-chunk, seamless cross-nc prefetch. Each 32-bit
// lane is the exact single-accumulator d-ascending fused-FMA chain
// (bit-identical to the validated round-2 kernel).
// ---------------------------------------------------------------------------
__global__ __launch_bounds__(256)
void vq_kernel(const float* __restrict__ x,
               const float* __restrict__ cb,
               float* __restrict__ out) {
    extern __shared__ __align__(16) char smem[];
    float*  As    = (float*)(smem + OFF_AS);    // [2][16][32]
    float*  Bsm   = (float*)(smem + OFF_BS);    // [2][16][284]
    float*  cns   = (float*)(smem + OFF_CNS);
    float*  xns   = (float*)(smem + OFF_XNS);
    float*  bestv = (float*)(smem + OFF_BV);
    int*    besti = (int*)(smem + OFF_BI);
    double* red   = (double*)(smem + OFF_RED);

    const int t  = threadIdx.x;
    const int tx = t & 15;          // code group (16 codes)
    const int ty = t >> 4;          // pixel group (2 px)
    const int p0   = blockIdx.x * 32;
    const int bimg = p0 >> 10;
    const int hwb  = p0 & 1023;
    const float* xb = x + (size_t)bimg * D_DIM * HW_DIM + hwb;

#pragma unroll
    for (int i = 0; i < 4; i++) cns[t + i * 256] = g_cn[t + i * 256];
    if (t < 32) {
        xns[t] = g_xn[p0 + t];
        bestv[t] = FLT_MAX; besti[t] = 0x7fffffff;
    }
    // ordered before first use by the barrier inside iteration 0

    // loader mappings
    const int dkA = t >> 4, pxA = (t & 15) * 2;      // A: row dk, 2 px
    const int cc  = t >> 2;                          // B: base code 0..63
    const int ds0 = (t & 3) * 4;                     //    4 rows
    const int col0 = bcol(cc);
    const int col1 = bcol(cc + 64);
    const int col2 = bcol(cc + 128);
    const int col3 = bcol(cc + 192);
    const int rcol = tx * 16 + 4 * (tx >> 1);        // B reader word base

    u64 acc2[2][8];
    float2 ra;
    float4 rb0, rb1, rb2, rb3;
    // prefetch it = 0 (nc=0, kc=0)
    ra  = *(const float2*)(xb + (size_t)dkA * HW_DIM + pxA);
    rb0 = *(const float4*)(cb + (size_t)(cc)       * D_DIM + ds0);
    rb1 = *(const float4*)(cb + (size_t)(cc + 64)  * D_DIM + ds0);
    rb2 = *(const float4*)(cb + (size_t)(cc + 128) * D_DIM + ds0);
    rb3 = *(const float4*)(cb + (size_t)(cc + 192) * D_DIM + ds0);

    for (int it = 0; it < 64; it++) {
        const int nc = it >> 4, kc = it & 15, buf = it & 1;
        float* Ab = As  + buf * (16 * 32);
        float* Bb = Bsm + buf * (16 * BPITCH);

        // store prefetched chunk (buffer consumed at it-2, barrier at it-1)
        *(float2*)(Ab + dkA * 32 + pxA) = ra;
#pragma unroll
        for (int j = 0; j < 4; j++) {
            float* row = Bb + (ds0 + j) * BPITCH;
            row[col0] = ((const float*)&rb0)[j];
            row[col1] = ((const float*)&rb1)[j];
            row[col2] = ((const float*)&rb2)[j];
            row[col3] = ((const float*)&rb3)[j];
        }
        __syncthreads();   // the ONLY barrier per iteration

        if (it < 63) {     // prefetch it+1 (crosses nc boundaries seamlessly)
            const int kn = (it + 1) & 15, nn = (it + 1) >> 4;
            ra  = *(const float2*)(xb + (size_t)(kn * 16 + dkA) * HW_DIM + pxA);
            const float* cbn = cb + (size_t)nn * 256 * D_DIM + kn * 16 + ds0;
            rb0 = *(const float4*)(cbn + (size_t)(cc)       * D_DIM);
            rb1 = *(const float4*)(cbn + (size_t)(cc + 64)  * D_DIM);
            rb2 = *(const float4*)(cbn + (size_t)(cc + 128) * D_DIM);
            rb3 = *(const float4*)(cbn + (size_t)(cc + 192) * D_DIM);
        }

        if (kc == 0) {
#pragma unroll
            for (int i = 0; i < 2; i++)
#pragma unroll
                for (int j = 0; j < 8; j++) acc2[i][j] = 0ull;
        }

#pragma unroll
        for (int dk = 0; dk < 16; dk++) {
            float2 af = *(const float2*)(Ab + dk * 32 + ty * 2);  // broadcast
            const float* brow = Bb + dk * BPITCH + rcol;
            ulonglong2 bq0 = *(const ulonglong2*)(brow);
            ulonglong2 bq1 = *(const ulonglong2*)(brow + 4);
            ulonglong2 bq2 = *(const ulonglong2*)(brow + 8);
            ulonglong2 bq3 = *(const ulonglong2*)(brow + 12);
            u64 bp[8] = {bq0.x, bq0.y, bq1.x, bq1.y,
                         bq2.x, bq2.y, bq3.x, bq3.y};
            u64 a0 = dup2(af.x), a1 = dup2(af.y);
#pragma unroll
            for (int jp = 0; jp < 8; jp++) {
                acc2[0][jp] = fma2(a0, bp[jp], acc2[0][jp]);
                acc2[1][jp] = fma2(a1, bp[jp], acc2[1][jp]);
            }
        }

        if (kc == 15) {
            // Epilogue: d2 = fl(fl(xn - 2*dot) + cn); lowest-index ties on
            // rounded values; shfl-reduce across 16-lane tx group.
            const int cbase = nc * 256;
#pragma unroll
            for (int i = 0; i < 2; i++) {
                const int r = ty * 2 + i;
                const float xn = xns[r];
                float bv = FLT_MAX;
                int   bi = 0x7fffffff;
#pragma unroll
                for (int jp = 0; jp < 8; jp++) {
                    const int c0 = cbase + tx * 16 + 2 * jp;
                    float vlo = lo2(acc2[i][jp]);
                    float vhi = hi2(acc2[i][jp]);
                    float d0 = __fadd_rn(__fadd_rn(xn, __fmul_rn(-2.f, vlo)), cns[c0]);
                    float d1 = __fadd_rn(__fadd_rn(xn, __fmul_rn(-2.f, vhi)), cns[c0 + 1]);
                    if (d0 < bv) { bv = d0; bi = c0; }
                    if (d1 < bv) { bv = d1; bi = c0 + 1; }
                }
#pragma unroll
                for (int off = 8; off > 0; off >>= 1) {
                    float ov = __shfl_down_sync(0xffffffffu, bv, off, 16);
                    int   oi = __shfl_down_sync(0xffffffffu, bi, off, 16);
                    if (ov < bv || (ov == bv && oi < bi)) { bv = ov; bi = oi; }
                }
                if (tx == 0) {   // unique lane per pixel row r -> no race
                    if (bv < bestv[r] || (bv == bestv[r] && bi < besti[r])) {
                        bestv[r] = bv; besti[r] = bi;
                    }
                }
            }
        }
    }
    __syncthreads();

    // Output: STE rounding fl(x + fl(q-x)); loss from fl(x-q)^2 in double.
    double lsum = 0.0;
#pragma unroll 4
    for (int m = 0; m < 32; m++) {
        int e  = m * 256 + t;
        int d  = e >> 5;
        int pp = e & 31;
        size_t addr = (size_t)(bimg * D_DIM + d) * HW_DIM + hwb + pp;
        float q  = cb[(size_t)besti[pp] * D_DIM + d];
        float xv = x[addr];
        out[addr] = __fadd_rn(xv, __fsub_rn(q, xv));
        float diff = __fsub_rn(xv, q);
        lsum += (double)__fmul_rn(diff, diff);
    }
    red[t] = lsum;
    __syncthreads();
    for (int s = 128; s > 0; s >>= 1) {
        if (t < s) red[t] += red[t + s];
        __syncthreads();
    }
    if (t == 0) g_partial[blockIdx.x] = red[0];
}

// ---------------------------------------------------------------------------
__global__ void finalize_kernel(float* __restrict__ out, int out_size) {
    __shared__ double red[512];
    int t = threadIdx.x;
    red[t] = g_partial[t] + g_partial[t + 512]
           + g_partial[t + 1024] + g_partial[t + 1536];
    __syncthreads();
    for (int s = 256; s > 0; s >>= 1) {
        if (t < s) red[t] += red[t + s];
        __syncthreads();
    }
    if (t == 0) {
        float m = (float)(red[0] / (double)TOT_ELEMS);
        float loss = (float)(1.25 * (double)m);
        for (int i = TOT_ELEMS; i < out_size; i++) out[i] = loss;
    }
}

// ---------------------------------------------------------------------------
extern "C" void kernel_launch(void* const* d_in, const int* in_sizes, int n_in,
                              void* d_out, int out_size) {
    const float* x  = (const float*)d_in[0];
    const float* cb = (const float*)d_in[1];
    float* out = (float*)d_out;

    cudaFuncSetAttribute(vq_kernel,
                         cudaFuncAttributeMaxDynamicSharedMemorySize, SMEMB);

    cnorm_kernel<<<KCODE / 256, 256>>>(cb);
    xnorm_kernel<<<64, 256>>>(x);
    vq_kernel<<<NCTA, 256, SMEMB>>>(x, cb, out);
    finalize_kernel<<<1, 512>>>(out, out_size);
}

// round 16
// speedup vs baseline: 1.8065x; 1.8065x over previous
#include <cuda_runtime.h>
#include <cfloat>
#include <stdint.h>

// x [64,256,32,32] f32, codebook [1024,256] f32
#define D_DIM   256
#define HW_DIM  1024
#define NPIX    65536
#define KCODE   1024
#define TOT_ELEMS 16777216

typedef unsigned long long u64;

// Scratch (device globals; allocation-free)
__device__ float  g_cn[KCODE];
__device__ float  g_xn[NPIX];
__device__ u64    g_key[NPIX];      // (d2_bits<<32)|code, atomicMin-merged
__device__ double g_partial[512];

// ===================== packed f32x2 helpers (sm_100+) =====================
__device__ __forceinline__ u64 fma2(u64 a, u64 b, u64 c) {
    u64 d;
    asm("fma.rn.f32x2 %0, %1, %2, %3;" : "=l"(d) : "l"(a), "l"(b), "l"(c));
    return d;
}
__device__ __forceinline__ u64 dup2(float v) {
    u64 d;
    asm("mov.b64 %0, {%1, %1};" : "=l"(d) : "f"(v));
    return d;
}
__device__ __forceinline__ float lo2(u64 v) {
    float l, h;
    asm("mov.b64 {%0, %1}, %2;" : "=f"(l), "=f"(h) : "l"(v));
    return l;
}
__device__ __forceinline__ float hi2(u64 v) {
    float l, h;
    asm("mov.b64 {%0, %1}, %2;" : "=f"(l), "=f"(h) : "l"(v));
    return h;
}

// B smem column swizzle (round-9 validated): code c at word c + 4*(c>>5);
// 8-lane LDS.128 phases cover all 32 banks. Row pitch 140 words.
#define BPITCH 140
__device__ __forceinline__ int bcol(int c) { return c + 4 * (c >> 5); }

// ---------------------------------------------------------------------------
// norms (scalar-sequential order — bit-exact-validated in round 2)
// ---------------------------------------------------------------------------
__global__ void cnorm_kernel(const float* __restrict__ cb) {
    int k = blockIdx.x * 256 + threadIdx.x;
    const float* row = cb + (size_t)k * D_DIM;
    float s = 0.f;
    for (int d = 0; d < D_DIM; d++) s = __fadd_rn(s, __fmul_rn(row[d], row[d]));
    g_cn[k] = s;
}
__global__ void xnorm_kernel(const float* __restrict__ x) {
    int b = blockIdx.x, t = threadIdx.x;
    const float* xb = x + (size_t)b * D_DIM * HW_DIM + t * 4;
    float sa[4] = {0.f, 0.f, 0.f, 0.f};
    for (int d = 0; d < D_DIM; d++) {
        float4 v = *(const float4*)(xb + (size_t)d * HW_DIM);
        sa[0] = __fadd_rn(sa[0], __fmul_rn(v.x, v.x));
        sa[1] = __fadd_rn(sa[1], __fmul_rn(v.y, v.y));
        sa[2] = __fadd_rn(sa[2], __fmul_rn(v.z, v.z));
        sa[3] = __fadd_rn(sa[3], __fmul_rn(v.w, v.w));
    }
    int p = b * HW_DIM + t * 4;
#pragma unroll
    for (int j = 0; j < 4; j++) {
        g_xn[p + j]  = sa[j];
        g_key[p + j] = ~0ull;
    }
}

// ---------------------------------------------------------------------------
// Main VQ: round-13 FFMA2 core verbatim, but each CTA covers a 256-code
// quarter (2 nc chunks). Grid = 512 px-blocks x 4 quarters = 2048 jobs ->
// 98.9% slot packing. Cross-CTA argmin merged via u64 atomicMin (d2 > 0
// guaranteed: xn ~ 256 >> |2 dot|). Bit-exact chain identical to round 2.
// ---------------------------------------------------------------------------
__global__ __launch_bounds__(256, 2)
void vq_kernel(const float* __restrict__ x,
               const float* __restrict__ cb) {
    __shared__ __align__(16) float As[2][16][128];     // 16KB
    __shared__ __align__(16) float Bs[2][16][BPITCH];  // 17.5KB
    __shared__ float cns[KCODE];
    __shared__ float xns[128];
    __shared__ float bestv[128];
    __shared__ int   besti[128];

    const int t  = threadIdx.x;
    const int tx = t & 15;
    const int ty = t >> 4;
    const int pb = blockIdx.x & 511;       // pixel block
    const int qq = blockIdx.x >> 9;        // code quarter 0..3
    const int p0   = pb * 128;
    const int bimg = p0 >> 10;
    const int hwb  = p0 & 1023;
    const int code0 = qq * 256;            // this CTA's code range base
    const float* xb = x + (size_t)bimg * D_DIM * HW_DIM + hwb;

#pragma unroll
    for (int i = 0; i < 4; i++) cns[t + i * 256] = g_cn[t + i * 256];
    if (t < 128) {
        xns[t] = g_xn[p0 + t];
        bestv[t] = FLT_MAX; besti[t] = 0x7fffffff;
    }
    // ordered before first use by the barrier inside iteration 0

    // loader mappings (round 9/13)
    const int dkA0 = t >> 5, dkA1 = dkA0 + 8;
    const int ppA  = (t & 31) * 4;
    const int cc0  = t >> 2, cc1 = cc0 + 64;
    const int ds0  = (t & 3) * 4;
    const int col0 = bcol(cc0), col1 = bcol(cc1);
    const int rcol = tx * 8 + 4 * (tx >> 2);

    u64 acc2[8][4];
    float4 ra0, ra1, rb0, rb1;
    // prefetch it = 0 (nc=0, kc=0)
    ra0 = *(const float4*)(xb + (size_t)dkA0 * HW_DIM + ppA);
    ra1 = *(const float4*)(xb + (size_t)dkA1 * HW_DIM + ppA);
    rb0 = *(const float4*)(cb + (size_t)(code0 + cc0) * D_DIM + ds0);
    rb1 = *(const float4*)(cb + (size_t)(code0 + cc1) * D_DIM + ds0);

    for (int it = 0; it < 32; it++) {
        const int nc = it >> 4, kc = it & 15, buf = it & 1;

        // store prefetched chunk (buffer consumed at it-2, barrier at it-1)
        *(float4*)&As[buf][dkA0][ppA] = ra0;
        *(float4*)&As[buf][dkA1][ppA] = ra1;
        Bs[buf][ds0 + 0][col0] = rb0.x; Bs[buf][ds0 + 1][col0] = rb0.y;
        Bs[buf][ds0 + 2][col0] = rb0.z; Bs[buf][ds0 + 3][col0] = rb0.w;
        Bs[buf][ds0 + 0][col1] = rb1.x; Bs[buf][ds0 + 1][col1] = rb1.y;
        Bs[buf][ds0 + 2][col1] = rb1.z; Bs[buf][ds0 + 3][col1] = rb1.w;
        __syncthreads();   // the ONLY barrier per iteration

        if (it < 31) {     // prefetch it+1 (crosses nc boundary seamlessly)
            const int kn = (it + 1) & 15, nn = (it + 1) >> 4;
            ra0 = *(const float4*)(xb + (size_t)(kn * 16 + dkA0) * HW_DIM + ppA);
            ra1 = *(const float4*)(xb + (size_t)(kn * 16 + dkA1) * HW_DIM + ppA);
            rb0 = *(const float4*)(cb + (size_t)(code0 + nn * 128 + cc0) * D_DIM + kn * 16 + ds0);
            rb1 = *(const float4*)(cb + (size_t)(code0 + nn * 128 + cc1) * D_DIM + kn * 16 + ds0);
        }

        if (kc == 0) {
#pragma unroll
            for (int i = 0; i < 8; i++)
#pragma unroll
                for (int j = 0; j < 4; j++) acc2[i][j] = 0ull;
        }

        // round-13 dk loop, reading buffer `buf`
#pragma unroll
        for (int dk = 0; dk < 16; dk++) {
            float4 af0 = *(const float4*)&As[buf][dk][ty * 8];       // broadcast
            float4 af1 = *(const float4*)&As[buf][dk][ty * 8 + 4];
            ulonglong2 bq0 = *(const ulonglong2*)&Bs[buf][dk][rcol];
            ulonglong2 bq1 = *(const ulonglong2*)&Bs[buf][dk][rcol + 4];
            u64 bp[4] = {bq0.x, bq0.y, bq1.x, bq1.y};
            float av[8] = {af0.x, af0.y, af0.z, af0.w,
                           af1.x, af1.y, af1.z, af1.w};
#pragma unroll
            for (int i = 0; i < 8; i++) {
                u64 ad = dup2(av[i]);
#pragma unroll
                for (int jp = 0; jp < 4; jp++)
                    acc2[i][jp] = fma2(ad, bp[jp], acc2[i][jp]);
            }
        }

        if (kc == 15) {
            // Epilogue: d2 = fl(fl(xn - 2*dot) + cn); lowest-index ties on
            // rounded values; shfl-reduce across 16-lane tx group.
            const int cbase = code0 + nc * 128;
#pragma unroll
            for (int i = 0; i < 8; i++) {
                const int r = ty * 8 + i;
                const float xn = xns[r];
                float bv = FLT_MAX;
                int   bi = 0x7fffffff;
#pragma unroll
                for (int jp = 0; jp < 4; jp++) {
                    const int c0 = cbase + tx * 8 + 2 * jp;
                    float vlo = lo2(acc2[i][jp]);
                    float vhi = hi2(acc2[i][jp]);
                    float d0 = __fadd_rn(__fadd_rn(xn, __fmul_rn(-2.f, vlo)), cns[c0]);
                    float d1 = __fadd_rn(__fadd_rn(xn, __fmul_rn(-2.f, vhi)), cns[c0 + 1]);
                    if (d0 < bv) { bv = d0; bi = c0; }
                    if (d1 < bv) { bv = d1; bi = c0 + 1; }
                }
#pragma unroll
                for (int off = 8; off > 0; off >>= 1) {
                    float ov = __shfl_down_sync(0xffffffffu, bv, off, 16);
                    int   oi = __shfl_down_sync(0xffffffffu, bi, off, 16);
                    if (ov < bv || (ov == bv && oi < bi)) { bv = ov; bi = oi; }
                }
                if (tx == 0) {
                    if (bv < bestv[r] || (bv == bestv[r] && bi < besti[r])) {
                        bestv[r] = bv; besti[r] = bi;
                    }
                }
            }
        }
    }
    __syncthreads();

    // Merge this quarter's result: d2 > 0 so float bit order == value order;
    // key = (d2_bits<<32)|code gives min-d2 then lowest-code — exact tie rule.
    if (t < 128) {
        u64 key = ((u64)__float_as_uint(bestv[t]) << 32) | (unsigned)besti[t];
        atomicMin(&g_key[p0 + t], key);
    }
}

// ---------------------------------------------------------------------------
// Output: gather + STE rounding + loss partial
// ---------------------------------------------------------------------------
__global__ __launch_bounds__(256)
void output_kernel(const float* __restrict__ x, const float* __restrict__ cb,
                   float* __restrict__ out) {
    __shared__ int besti[128];
    __shared__ double red[256];
    const int t = threadIdx.x;
    const int p0 = blockIdx.x * 128, bimg = p0 >> 10, hwb = p0 & 1023;
    if (t < 128) besti[t] = (int)(unsigned)(g_key[p0 + t] & 0xffffffffull);
    __syncthreads();

    double lsum = 0.0;
#pragma unroll 4
    for (int m = 0; m < 32; m++) {
        int e4 = m * 256 + t;
        int d  = e4 >> 5;
        int pp = (e4 & 31) * 4;
        size_t addr = (size_t)(bimg * D_DIM + d) * HW_DIM + hwb + pp;
        float4 xv = *(const float4*)(x + addr);
        float q0 = cb[(size_t)besti[pp + 0] * D_DIM + d];
        float q1 = cb[(size_t)besti[pp + 1] * D_DIM + d];
        float q2 = cb[(size_t)besti[pp + 2] * D_DIM + d];
        float q3 = cb[(size_t)besti[pp + 3] * D_DIM + d];
        float4 o;
        o.x = __fadd_rn(xv.x, __fsub_rn(q0, xv.x));
        o.y = __fadd_rn(xv.y, __fsub_rn(q1, xv.y));
        o.z = __fadd_rn(xv.z, __fsub_rn(q2, xv.z));
        o.w = __fadd_rn(xv.w, __fsub_rn(q3, xv.w));
        *(float4*)(out + addr) = o;
        float d0 = __fsub_rn(xv.x, q0), d1 = __fsub_rn(xv.y, q1);
        float d2 = __fsub_rn(xv.z, q2), d3 = __fsub_rn(xv.w, q3);
        lsum += (double)__fmul_rn(d0, d0) + (double)__fmul_rn(d1, d1)
              + (double)__fmul_rn(d2, d2) + (double)__fmul_rn(d3, d3);
    }
    red[t] = lsum;
    __syncthreads();
    for (int s = 128; s > 0; s >>= 1) {
        if (t < s) red[t] += red[t + s];
        __syncthreads();
    }
    if (t == 0) g_partial[blockIdx.x] = red[0];
}

// ---------------------------------------------------------------------------
__global__ void finalize_kernel(float* __restrict__ out, int out_size) {
    __shared__ double red[512];
    int t = threadIdx.x;
    red[t] = g_partial[t];
    __syncthreads();
    for (int s = 256; s > 0; s >>= 1) {
        if (t < s) red[t] += red[t + s];
        __syncthreads();
    }
    if (t == 0) {
        float m = (float)(red[0] / (double)TOT_ELEMS);
        float loss = (float)(1.25 * (double)m);
        for (int i = TOT_ELEMS; i < out_size; i++) out[i] = loss;
    }
}

// ---------------------------------------------------------------------------
extern "C" void kernel_launch(void* const* d_in, const int* in_sizes, int n_in,
                              void* d_out, int out_size) {
    const float* x  = (const float*)d_in[0];
    const float* cb = (const float*)d_in[1];
    float* out = (float*)d_out;

    cnorm_kernel<<<KCODE / 256, 256>>>(cb);
    xnorm_kernel<<<64, 256>>>(x);
    vq_kernel<<<2048, 256>>>(x, cb);
    output_kernel<<<NPIX / 128, 256>>>(x, cb, out);
    finalize_kernel<<<1, 512>>>(out, out_size);
}